// round 9
// baseline (speedup 1.0000x reference)
#include <cuda_runtime.h>
#include <cuda_bf16.h>
#include <cstdint>

#define N_NODES 50000
#define N_EDGES 800000
#define SCAN_BLOCKS 196

// ---------------- scratch (device globals; no runtime allocation) -------------
__device__ float g_deg[N_NODES];
__device__ float g_dinv[N_NODES];
__device__ int   g_count[N_NODES];
__device__ int   g_off[N_NODES + 1];
__device__ int   g_fill[N_NODES];
__device__ int   g_bsum[SCAN_BLOCKS];
__device__ int   g_btop[SCAN_BLOCKS];
__device__ int   g_elist[N_EDGES];
__device__ float g_h1[(size_t)N_NODES * 64];
__device__ float g_s[N_NODES];
__device__ float g_sagg[N_NODES];
__device__ float g_v[64];     // gcn2_W @ w_gnn
__device__ float g_u[512];    // fc2_W  @ w_mlp
__device__ float g_cconst;    // fcf_b + fc2_b.w_mlp + gcn2_b.w_gnn
__device__ float g_mlp[2][N_NODES];                    // per-N-half MLP partials
// bf16 hi/lo operands
__device__ __nv_bfloat16 g_Ah[(size_t)N_NODES * 256];  // uf hi
__device__ __nv_bfloat16 g_Al[(size_t)N_NODES * 256];  // uf lo
__device__ __nv_bfloat16 g_Bh[512 * 256];              // fc1_W^T hi  [n][k]
__device__ __nv_bfloat16 g_Bl[512 * 256];              // fc1_W^T lo
__device__ __nv_bfloat16 g_B1h[64 * 256];              // gcn1_W^T hi
__device__ __nv_bfloat16 g_B1l[64 * 256];              // gcn1_W^T lo

// ---------------- PTX helpers (baseline sm_80+ features only) ------------------
__device__ __forceinline__ uint32_t smem_u32(const void* p) {
    uint32_t a;
    asm("{ .reg .u64 t; cvta.to.shared.u64 t, %1; cvt.u32.u64 %0, t; }" : "=r"(a) : "l"(p));
    return a;
}
#define LDSM4(r0, r1, r2, r3, a) \
    asm volatile("ldmatrix.sync.aligned.m8n8.x4.shared.b16 {%0,%1,%2,%3}, [%4];" \
                 : "=r"(r0), "=r"(r1), "=r"(r2), "=r"(r3) : "r"(a))
#define LDSM2(r0, r1, a) \
    asm volatile("ldmatrix.sync.aligned.m8n8.x2.shared.b16 {%0,%1}, [%2];" \
                 : "=r"(r0), "=r"(r1) : "r"(a))
#define MMA(c, a, b0, b1) \
    asm volatile("mma.sync.aligned.m16n8k16.row.col.f32.bf16.bf16.f32 " \
                 "{%0,%1,%2,%3},{%4,%5,%6,%7},{%8,%9},{%0,%1,%2,%3};" \
                 : "+f"((c)[0]), "+f"((c)[1]), "+f"((c)[2]), "+f"((c)[3]) \
                 : "r"((a)[0]), "r"((a)[1]), "r"((a)[2]), "r"((a)[3]), "r"(b0), "r"(b1))

__device__ __forceinline__ uint32_t pack_bf(__nv_bfloat16 a, __nv_bfloat16 b) {
    __nv_bfloat162 t(a, b);
    return *(uint32_t*)&t;
}
__device__ __forceinline__ void split4(float4 v, uint2& hh, uint2& ll) {
    float vv[4] = {v.x, v.y, v.z, v.w};
    __nv_bfloat16 h[4], l[4];
    #pragma unroll
    for (int j = 0; j < 4; j++) {
        h[j] = __float2bfloat16(vv[j]);
        l[j] = __float2bfloat16(vv[j] - __bfloat162float(h[j]));
    }
    hh = make_uint2(pack_bf(h[0], h[1]), pack_bf(h[2], h[3]));
    ll = make_uint2(pack_bf(l[0], l[1]), pack_bf(l[2], l[3]));
}

// ---------------- tiny precompute: collapse trailing GEMMs --------------------
__global__ void precompute_kernel(const float* __restrict__ g2W, const float* __restrict__ g2b,
                                  const float* __restrict__ f2W, const float* __restrict__ f2b,
                                  const float* __restrict__ ffW, const float* __restrict__ ffb) {
    int tid = threadIdx.x;
    if (tid < 512) {
        float acc = 0.f;
        #pragma unroll 8
        for (int c = 0; c < 64; c++) acc += f2W[tid * 64 + c] * ffW[c];
        g_u[tid] = acc;
    }
    if (tid < 64) {
        float acc = 0.f;
        #pragma unroll 8
        for (int c = 0; c < 64; c++) acc += g2W[tid * 64 + c] * ffW[64 + c];
        g_v[tid] = acc;
    }
    if (tid == 0) {
        float acc = ffb[0];
        for (int c = 0; c < 64; c++) acc += f2b[c] * ffW[c] + g2b[c] * ffW[64 + c];
        g_cconst = acc;
    }
}

__global__ void convert_W_kernel(const float* __restrict__ f1W, const float* __restrict__ g1W) {
    int idx = blockIdx.x * blockDim.x + threadIdx.x;
    if (idx < 256 * 512) {
        int k = idx / 512, n = idx % 512;
        float w = f1W[idx];
        __nv_bfloat16 h = __float2bfloat16(w);
        g_Bh[n * 256 + k] = h;
        g_Bl[n * 256 + k] = __float2bfloat16(w - __bfloat162float(h));
    } else if (idx < 256 * 512 + 256 * 64) {
        int i2 = idx - 256 * 512;
        int k = i2 / 64, n = i2 % 64;
        float w = g1W[i2];
        __nv_bfloat16 h = __float2bfloat16(w);
        g_B1h[n * 256 + k] = h;
        g_B1l[n * 256 + k] = __float2bfloat16(w - __bfloat162float(h));
    }
}

__global__ void convertA_kernel(const float* __restrict__ uf) {
    int i = blockIdx.x * blockDim.x + threadIdx.x;   // float4 index
    if (i < N_NODES * 64) {
        uint2 hh, ll;
        split4(((const float4*)uf)[i], hh, ll);
        *(uint2*)(g_Ah + (size_t)i * 4) = hh;
        *(uint2*)(g_Al + (size_t)i * 4) = ll;
    }
}

// ---------------- graph prep --------------------------------------------------
__global__ void init_kernel() {
    int i = blockIdx.x * blockDim.x + threadIdx.x;
    if (i < N_NODES) { g_deg[i] = 1.0f; g_count[i] = 0; }
}
__global__ void edge_prep_kernel(const int* __restrict__ ei, const float* __restrict__ ea) {
    int e = blockIdx.x * blockDim.x + threadIdx.x;
    if (e < N_EDGES) {
        int dst = ei[N_EDGES + e];
        atomicAdd(&g_deg[dst], ea[e]);
        atomicAdd(&g_count[dst], 1);
    }
}
__global__ void dinv_kernel() {
    int i = blockIdx.x * blockDim.x + threadIdx.x;
    if (i < N_NODES) g_dinv[i] = rsqrtf(g_deg[i]);
}

// parallel 3-phase scan: per-block exclusive scan + block totals
__global__ void scan_blocks_kernel() {
    __shared__ int wsum[8];
    int tid = threadIdx.x, lane = tid & 31, w = tid >> 5;
    int i = blockIdx.x * 256 + tid;
    int v = (i < N_NODES) ? g_count[i] : 0;
    int x = v;
    #pragma unroll
    for (int o = 1; o < 32; o <<= 1) {
        int y = __shfl_up_sync(0xffffffffu, x, o);
        if (lane >= o) x += y;
    }
    if (lane == 31) wsum[w] = x;
    __syncthreads();
    if (w == 0 && lane < 8) {
        int t = wsum[lane];
        #pragma unroll
        for (int o = 1; o < 8; o <<= 1) {
            int y = __shfl_up_sync(0xffu, t, o);
            if (lane >= o) t += y;
        }
        wsum[lane] = t;
    }
    __syncthreads();
    int wpre = (w == 0) ? 0 : wsum[w - 1];
    if (i < N_NODES) g_off[i] = wpre + x - v;
    if (tid == 255) g_bsum[blockIdx.x] = wsum[7];
}
__global__ void scan_tops_kernel() {
    __shared__ int wsum[8];
    int tid = threadIdx.x, lane = tid & 31, w = tid >> 5;
    int v = (tid < SCAN_BLOCKS) ? g_bsum[tid] : 0;
    int x = v;
    #pragma unroll
    for (int o = 1; o < 32; o <<= 1) {
        int y = __shfl_up_sync(0xffffffffu, x, o);
        if (lane >= o) x += y;
    }
    if (lane == 31) wsum[w] = x;
    __syncthreads();
    if (w == 0 && lane < 8) {
        int t = wsum[lane];
        #pragma unroll
        for (int o = 1; o < 8; o <<= 1) {
            int y = __shfl_up_sync(0xffu, t, o);
            if (lane >= o) t += y;
        }
        wsum[lane] = t;
    }
    __syncthreads();
    int wpre = (w == 0) ? 0 : wsum[w - 1];
    if (tid < SCAN_BLOCKS) g_btop[tid] = wpre + x - v;
}
__global__ void scan_apply_kernel() {
    int i = blockIdx.x * 256 + threadIdx.x;
    if (i < N_NODES) {
        int o = g_off[i] + g_btop[blockIdx.x];
        g_off[i] = o;
        g_fill[i] = o;
    }
    if (i == 0) g_off[N_NODES] = N_EDGES;   // sum of all in-degrees
}

__global__ void fill_kernel(const int* __restrict__ ei) {
    int e = blockIdx.x * blockDim.x + threadIdx.x;
    if (e < N_EDGES) {
        int dst = ei[N_EDGES + e];
        int pos = atomicAdd(&g_fill[dst], 1);
        g_elist[pos] = e;
    }
}

// ---------------- GEMM1 (mma.sync bf16, pass-fused): h1 = x @ gcn1_W ----------
// CTA: M=64, N=64, K=256 resident. 256 thr / 8 warps, warp tile m64 x n8.
__global__ __launch_bounds__(256) void gemm1_mma_kernel(const float* __restrict__ x) {
    extern __shared__ char smem[];
    const int AH = 0, AL = 33792, BH = 67584, BL = 101376;
    uint32_t sb = smem_u32(smem);
    int tid = threadIdx.x, w = tid >> 5, lane = tid & 31;
    int row0 = blockIdx.x * 64;

    for (int i = tid; i < 64 * 64; i += 256) {
        int r = i >> 6, c4 = i & 63;
        float4 v = make_float4(0.f, 0.f, 0.f, 0.f);
        int row = row0 + r;
        if (row < N_NODES) v = *(const float4*)(x + (size_t)row * 256 + c4 * 4);
        uint2 hh, ll;
        split4(v, hh, ll);
        *(uint2*)(smem + AH + r * 528 + c4 * 8) = hh;
        *(uint2*)(smem + AL + r * 528 + c4 * 8) = ll;
    }
    for (int i = tid; i < 64 * 32; i += 256) {
        int n = i >> 5, j = i & 31;
        *(uint4*)(smem + BH + n * 528 + j * 16) = *(const uint4*)(g_B1h + n * 256 + j * 8);
        *(uint4*)(smem + BL + n * 528 + j * 16) = *(const uint4*)(g_B1l + n * 256 + j * 8);
    }
    __syncthreads();

    float c[4][4] = {};
    int ll16 = lane & 15;
    #pragma unroll 2
    for (int ks = 0; ks < 16; ks++) {
        int kg = ks * 16;
        uint32_t ah[4][4], al[4][4];
        #pragma unroll
        for (int mt = 0; mt < 4; mt++) {
            uint32_t off = (mt * 16 + ll16) * 528 + kg * 2 + ((lane >> 4) & 1) * 16;
            LDSM4(ah[mt][0], ah[mt][1], ah[mt][2], ah[mt][3], sb + AH + off);
            LDSM4(al[mt][0], al[mt][1], al[mt][2], al[mt][3], sb + AL + off);
        }
        uint32_t boff = (w * 8 + (ll16 & 7)) * 528 + kg * 2 + ((ll16 >> 3) & 1) * 16;
        uint32_t bh0, bh1, bl0, bl1;
        LDSM2(bh0, bh1, sb + BH + boff);
        LDSM2(bl0, bl1, sb + BL + boff);
        #pragma unroll
        for (int mt = 0; mt < 4; mt++) {
            MMA(c[mt], ah[mt], bh0, bh1);
            MMA(c[mt], al[mt], bh0, bh1);
            MMA(c[mt], ah[mt], bl0, bl1);
        }
    }
    int g = lane >> 2, tg = lane & 3;
    int col = w * 8 + tg * 2;
    #pragma unroll
    for (int mt = 0; mt < 4; mt++) {
        #pragma unroll
        for (int h = 0; h < 2; h++) {
            int row = row0 + mt * 16 + h * 8 + g;
            if (row < N_NODES)
                *(float2*)(g_h1 + (size_t)row * 64 + col) = make_float2(c[mt][h * 2], c[mt][h * 2 + 1]);
        }
    }
}

// ---------------- fused: CSR gather + self-loop + bias + relu + dot(v) --------
__global__ void gather1_kernel(const int* __restrict__ ei, const float* __restrict__ ea,
                               const float* __restrict__ b1) {
    int gtid = blockIdx.x * blockDim.x + threadIdx.x;
    int node = gtid >> 5;
    int lane = gtid & 31;
    if (node >= N_NODES) return;
    float dinvi = g_dinv[node];
    float d2 = dinvi * dinvi;
    const float* h1n = g_h1 + (size_t)node * 64;
    float acc0 = h1n[lane] * d2;
    float acc1 = h1n[lane + 32] * d2;
    int beg = g_off[node], end = g_off[node + 1];
    for (int j = beg; j < end; j++) {
        int e = g_elist[j];
        int src = ei[e];
        float norm = ea[e] * g_dinv[src] * dinvi;
        const float* h1s = g_h1 + (size_t)src * 64;
        acc0 += h1s[lane] * norm;
        acc1 += h1s[lane + 32] * norm;
    }
    float gg0 = fmaxf(acc0 + b1[lane], 0.f);
    float gg1 = fmaxf(acc1 + b1[lane + 32], 0.f);
    float p = gg0 * g_v[lane] + gg1 * g_v[lane + 32];
    #pragma unroll
    for (int o = 16; o > 0; o >>= 1) p += __shfl_xor_sync(0xffffffffu, p, o);
    if (lane == 0) { g_s[node] = p; g_sagg[node] = d2 * p; }
}

// ---------------- scalar layer-2 aggregation ----------------------------------
__global__ void gather2_kernel(const int* __restrict__ ei, const float* __restrict__ ea) {
    int i = blockIdx.x * blockDim.x + threadIdx.x;
    if (i >= N_NODES) return;
    float dinvi = g_dinv[i];
    float acc = g_sagg[i];
    int beg = g_off[i], end = g_off[i + 1];
    for (int j = beg; j < end; j++) {
        int e = g_elist[j];
        int src = ei[e];
        acc += ea[e] * g_dinv[src] * dinvi * g_s[src];
    }
    g_sagg[i] = acc;
}

// ---------------- fused MLP (mma.sync bf16, pass-fused, M=64) -----------------
// CTA: M=64, N=256 (blockIdx.y half of 512), K chunks of 64. 256 thr / 8 warps,
// warp tile m64 x n32. SMEM: Ah/Al 33792 ea | Bh/Bl 36864 ea | b1s/us 1K ea |
// sred 2304 = 145664 B -> 1 CTA/SM, halved B L2 traffic vs M=32.
__global__ __launch_bounds__(256) void mlp_mma_kernel(const float* __restrict__ b1) {
    extern __shared__ char smem[];
    const int AH = 0, AL = 33792, BH = 67584, BL = 104448;
    const int B1S = 141312, US = 142336, SRED = 143360;
    uint32_t sb = smem_u32(smem);
    int tid = threadIdx.x, w = tid >> 5, lane = tid & 31;
    int row0 = blockIdx.x * 64;
    int ngrp = blockIdx.y;

    float* b1s = (float*)(smem + B1S);
    float* us  = (float*)(smem + US);
    float* sred = (float*)(smem + SRED);
    if (tid < 256) { b1s[tid] = b1[ngrp * 256 + tid]; us[tid] = g_u[ngrp * 256 + tid]; }

    // stage A (pre-split bf16 hi/lo), full K=256: 64 rows x 512B
    for (int i = tid; i < 2048; i += 256) {
        int r = i >> 5, c = i & 31;
        int row = row0 + r;
        uint4 vh = make_uint4(0, 0, 0, 0), vl = vh;
        if (row < N_NODES) {
            vh = *(const uint4*)(g_Ah + (size_t)row * 256 + c * 8);
            vl = *(const uint4*)(g_Al + (size_t)row * 256 + c * 8);
        }
        *(uint4*)(smem + AH + r * 528 + c * 16) = vh;
        *(uint4*)(smem + AL + r * 528 + c * 16) = vl;
    }

    float c[4][4][4] = {};
    int ll16 = lane & 15;
    int sub = (lane >> 3) & 3;

    #pragma unroll 1
    for (int ch = 0; ch < 4; ch++) {
        __syncthreads();
        // stage B chunk: 256 n-rows x 64 k (stride 144B)
        for (int i = tid; i < 2048; i += 256) {
            int n = i >> 3, j = i & 7;
            int kglob = ch * 64 + j * 8;
            *(uint4*)(smem + BH + n * 144 + j * 16) =
                *(const uint4*)(g_Bh + (size_t)(ngrp * 256 + n) * 256 + kglob);
            *(uint4*)(smem + BL + n * 144 + j * 16) =
                *(const uint4*)(g_Bl + (size_t)(ngrp * 256 + n) * 256 + kglob);
        }
        __syncthreads();

        #pragma unroll
        for (int ks = 0; ks < 4; ks++) {
            int kk = ks * 16;
            int kg = ch * 64 + kk;
            uint32_t ah[4][4], al[4][4];
            #pragma unroll
            for (int mt = 0; mt < 4; mt++) {
                uint32_t off = (mt * 16 + ll16) * 528 + kg * 2 + ((lane >> 4) & 1) * 16;
                LDSM4(ah[mt][0], ah[mt][1], ah[mt][2], ah[mt][3], sb + AH + off);
                LDSM4(al[mt][0], al[mt][1], al[mt][2], al[mt][3], sb + AL + off);
            }
            uint32_t bh[4][2], bl[4][2];
            #pragma unroll
            for (int ntp = 0; ntp < 2; ntp++) {
                int noff = w * 32 + ntp * 16 + ((sub & 2) ? 8 : 0) + (lane & 7);
                uint32_t boff = noff * 144 + kk * 2 + (sub & 1) * 16;
                uint32_t r0, r1, r2, r3;
                LDSM4(r0, r1, r2, r3, sb + BH + boff);
                bh[ntp * 2][0] = r0; bh[ntp * 2][1] = r1;
                bh[ntp * 2 + 1][0] = r2; bh[ntp * 2 + 1][1] = r3;
                LDSM4(r0, r1, r2, r3, sb + BL + boff);
                bl[ntp * 2][0] = r0; bl[ntp * 2][1] = r1;
                bl[ntp * 2 + 1][0] = r2; bl[ntp * 2 + 1][1] = r3;
            }
            #pragma unroll
            for (int mt = 0; mt < 4; mt++)
                #pragma unroll
                for (int nt = 0; nt < 4; nt++) {
                    MMA(c[mt][nt], ah[mt], bh[nt][0], bh[nt][1]);
                    MMA(c[mt][nt], al[mt], bh[nt][0], bh[nt][1]);
                    MMA(c[mt][nt], ah[mt], bl[nt][0], bl[nt][1]);
                }
        }
    }

    // epilogue: bias + relu + dot(u); quad-shuffle -> smem -> per-half write
    int g = lane >> 2, tg = lane & 3;
    #pragma unroll
    for (int mt = 0; mt < 4; mt++) {
        float rs[2] = {0.f, 0.f};
        #pragma unroll
        for (int nt = 0; nt < 4; nt++) {
            int col = w * 32 + nt * 8 + tg * 2;
            float bb0 = b1s[col], uu0 = us[col];
            float bb1 = b1s[col + 1], uu1 = us[col + 1];
            #pragma unroll
            for (int h = 0; h < 2; h++) {
                float h0 = c[mt][nt][h * 2] + bb0;
                float h1 = c[mt][nt][h * 2 + 1] + bb1;
                if (h0 > 0.f) rs[h] += h0 * uu0;
                if (h1 > 0.f) rs[h] += h1 * uu1;
            }
        }
        #pragma unroll
        for (int h = 0; h < 2; h++) {
            rs[h] += __shfl_xor_sync(0xffffffffu, rs[h], 1);
            rs[h] += __shfl_xor_sync(0xffffffffu, rs[h], 2);
            if (tg == 0) sred[(mt * 16 + h * 8 + g) * 9 + w] = rs[h];
        }
    }
    __syncthreads();
    if (tid < 64) {
        float sum = 0.f;
        #pragma unroll
        for (int t = 0; t < 8; t++) sum += sred[tid * 9 + t];
        int row = row0 + tid;
        if (row < N_NODES) g_mlp[ngrp][row] = sum;
    }
}

// ---------------- final combine -----------------------------------------------
__global__ void final_kernel(float* __restrict__ out) {
    int i = blockIdx.x * blockDim.x + threadIdx.x;
    if (i < N_NODES)
        out[i] = g_mlp[0][i] + g_mlp[1][i] + g_sagg[i] + g_cconst;
}

// ------------------------------------------------------------------------------
extern "C" void kernel_launch(void* const* d_in, const int* in_sizes, int n_in,
                              void* d_out, int out_size) {
    const float* x   = (const float*)d_in[0];
    const int*   ei  = (const int*)d_in[1];
    const float* ea  = (const float*)d_in[2];
    const float* uf  = (const float*)d_in[3];
    const float* g1W = (const float*)d_in[4];
    const float* g1b = (const float*)d_in[5];
    const float* g2W = (const float*)d_in[6];
    const float* g2b = (const float*)d_in[7];
    const float* f1W = (const float*)d_in[8];
    const float* f1b = (const float*)d_in[9];
    const float* f2W = (const float*)d_in[10];
    const float* f2b = (const float*)d_in[11];
    const float* ffW = (const float*)d_in[12];
    const float* ffb = (const float*)d_in[13];
    float* out = (float*)d_out;

    static cudaStream_t s1 = nullptr;
    static cudaEvent_t ev0, evG, ev1;
    if (!s1) {
        cudaStreamCreateWithFlags(&s1, cudaStreamNonBlocking);
        cudaEventCreateWithFlags(&ev0, cudaEventDisableTiming);
        cudaEventCreateWithFlags(&evG, cudaEventDisableTiming);
        cudaEventCreateWithFlags(&ev1, cudaEventDisableTiming);
        cudaFuncSetAttribute(gemm1_mma_kernel, cudaFuncAttributeMaxDynamicSharedMemorySize, 135168);
        cudaFuncSetAttribute(mlp_mma_kernel, cudaFuncAttributeMaxDynamicSharedMemorySize, 145664);
    }

    // fork: graph-prep branch on s1
    cudaEventRecord(ev0, 0);
    cudaStreamWaitEvent(s1, ev0, 0);
    init_kernel<<<(N_NODES + 255) / 256, 256, 0, s1>>>();
    edge_prep_kernel<<<(N_EDGES + 255) / 256, 256, 0, s1>>>(ei, ea);
    dinv_kernel<<<(N_NODES + 255) / 256, 256, 0, s1>>>();
    scan_blocks_kernel<<<SCAN_BLOCKS, 256, 0, s1>>>();
    scan_tops_kernel<<<1, 256, 0, s1>>>();
    scan_apply_kernel<<<SCAN_BLOCKS, 256, 0, s1>>>();
    fill_kernel<<<(N_EDGES + 255) / 256, 256, 0, s1>>>(ei);

    // main branch: weights + gemm1 first (gathers depend on it), then convertA + mlp
    precompute_kernel<<<1, 512>>>(g2W, g2b, f2W, f2b, ffW, ffb);
    convert_W_kernel<<<(256 * 512 + 256 * 64 + 255) / 256, 256>>>(f1W, g1W);
    gemm1_mma_kernel<<<(N_NODES + 63) / 64, 256, 135168>>>(x);
    cudaEventRecord(evG, 0);

    // s1 continues: gathers need gemm1 (h1) + precompute (g_v)
    cudaStreamWaitEvent(s1, evG, 0);
    gather1_kernel<<<((size_t)N_NODES * 32 + 255) / 256, 256, 0, s1>>>(ei, ea, g1b);
    gather2_kernel<<<(N_NODES + 255) / 256, 256, 0, s1>>>(ei, ea);
    cudaEventRecord(ev1, s1);

    // main branch: A-convert + big MLP GEMM overlap the whole graph branch
    convertA_kernel<<<(N_NODES * 64 + 255) / 256, 256>>>(uf);
    mlp_mma_kernel<<<dim3((N_NODES + 63) / 64, 2), 256, 145664>>>(f1b);

    // join + combine
    cudaStreamWaitEvent(0, ev1, 0);
    final_kernel<<<(N_NODES + 255) / 256, 256>>>(out);
}

// round 12
// speedup vs baseline: 1.0759x; 1.0759x over previous
#include <cuda_runtime.h>
#include <cuda_bf16.h>
#include <cstdint>

#define N_NODES 50000
#define N_EDGES 800000
#define SCAN_BLOCKS 196

// ---------------- scratch (device globals; no runtime allocation) -------------
__device__ float g_deg[N_NODES];
__device__ float g_dinv[N_NODES];
__device__ int   g_count[N_NODES];
__device__ int   g_off[N_NODES + 1];
__device__ int   g_fill[N_NODES];
__device__ int   g_bsum[SCAN_BLOCKS];
__device__ int   g_btop[SCAN_BLOCKS];
__device__ int   g_elist[N_EDGES];
__device__ float g_h1[(size_t)N_NODES * 64];
__device__ float g_s[N_NODES];
__device__ float g_sagg[N_NODES];
__device__ float g_v[64];     // gcn2_W @ w_gnn
__device__ float g_u[512];    // fc2_W  @ w_mlp
__device__ float g_cconst;    // fcf_b + fc2_b.w_mlp + gcn2_b.w_gnn
__device__ float g_mlp[2][N_NODES];                    // per-N-half MLP partials
// bf16 hi/lo operands
__device__ __nv_bfloat16 g_Ah[(size_t)N_NODES * 256];  // uf hi
__device__ __nv_bfloat16 g_Al[(size_t)N_NODES * 256];  // uf lo
__device__ __nv_bfloat16 g_Bh[512 * 256];              // fc1_W^T hi  [n][k]
__device__ __nv_bfloat16 g_Bl[512 * 256];              // fc1_W^T lo
__device__ __nv_bfloat16 g_B1h[64 * 256];              // gcn1_W^T hi
__device__ __nv_bfloat16 g_B1l[64 * 256];              // gcn1_W^T lo

// ---------------- PTX helpers (baseline sm_80+ features only) ------------------
__device__ __forceinline__ uint32_t smem_u32(const void* p) {
    uint32_t a;
    asm("{ .reg .u64 t; cvta.to.shared.u64 t, %1; cvt.u32.u64 %0, t; }" : "=r"(a) : "l"(p));
    return a;
}
#define LDSM4(r0, r1, r2, r3, a) \
    asm volatile("ldmatrix.sync.aligned.m8n8.x4.shared.b16 {%0,%1,%2,%3}, [%4];" \
                 : "=r"(r0), "=r"(r1), "=r"(r2), "=r"(r3) : "r"(a))
#define LDSM2(r0, r1, a) \
    asm volatile("ldmatrix.sync.aligned.m8n8.x2.shared.b16 {%0,%1}, [%2];" \
                 : "=r"(r0), "=r"(r1) : "r"(a))
#define MMA(c, a, b0, b1) \
    asm volatile("mma.sync.aligned.m16n8k16.row.col.f32.bf16.bf16.f32 " \
                 "{%0,%1,%2,%3},{%4,%5,%6,%7},{%8,%9},{%0,%1,%2,%3};" \
                 : "+f"((c)[0]), "+f"((c)[1]), "+f"((c)[2]), "+f"((c)[3]) \
                 : "r"((a)[0]), "r"((a)[1]), "r"((a)[2]), "r"((a)[3]), "r"(b0), "r"(b1))
#define CPA16(d, s, sz) \
    asm volatile("cp.async.cg.shared.global [%0], [%1], 16, %2;" :: "r"(d), "l"(s), "r"(sz))
#define CP_COMMIT() asm volatile("cp.async.commit_group;" ::: "memory")
#define CP_WAIT(n)  asm volatile("cp.async.wait_group %0;" :: "n"(n) : "memory")

__device__ __forceinline__ uint32_t pack_bf(__nv_bfloat16 a, __nv_bfloat16 b) {
    __nv_bfloat162 t(a, b);
    return *(uint32_t*)&t;
}
__device__ __forceinline__ void split4(float4 v, uint2& hh, uint2& ll) {
    float vv[4] = {v.x, v.y, v.z, v.w};
    __nv_bfloat16 h[4], l[4];
    #pragma unroll
    for (int j = 0; j < 4; j++) {
        h[j] = __float2bfloat16(vv[j]);
        l[j] = __float2bfloat16(vv[j] - __bfloat162float(h[j]));
    }
    hh = make_uint2(pack_bf(h[0], h[1]), pack_bf(h[2], h[3]));
    ll = make_uint2(pack_bf(l[0], l[1]), pack_bf(l[2], l[3]));
}

// ---------------- tiny precompute: collapse trailing GEMMs --------------------
__global__ void precompute_kernel(const float* __restrict__ g2W, const float* __restrict__ g2b,
                                  const float* __restrict__ f2W, const float* __restrict__ f2b,
                                  const float* __restrict__ ffW, const float* __restrict__ ffb) {
    int tid = threadIdx.x;
    if (tid < 512) {
        float acc = 0.f;
        #pragma unroll 8
        for (int c = 0; c < 64; c++) acc += f2W[tid * 64 + c] * ffW[c];
        g_u[tid] = acc;
    }
    if (tid < 64) {
        float acc = 0.f;
        #pragma unroll 8
        for (int c = 0; c < 64; c++) acc += g2W[tid * 64 + c] * ffW[64 + c];
        g_v[tid] = acc;
    }
    if (tid == 0) {
        float acc = ffb[0];
        for (int c = 0; c < 64; c++) acc += f2b[c] * ffW[c] + g2b[c] * ffW[64 + c];
        g_cconst = acc;
    }
}

__global__ void convert_W_kernel(const float* __restrict__ f1W, const float* __restrict__ g1W) {
    int idx = blockIdx.x * blockDim.x + threadIdx.x;
    if (idx < 256 * 512) {
        int k = idx / 512, n = idx % 512;
        float w = f1W[idx];
        __nv_bfloat16 h = __float2bfloat16(w);
        g_Bh[n * 256 + k] = h;
        g_Bl[n * 256 + k] = __float2bfloat16(w - __bfloat162float(h));
    } else if (idx < 256 * 512 + 256 * 64) {
        int i2 = idx - 256 * 512;
        int k = i2 / 64, n = i2 % 64;
        float w = g1W[i2];
        __nv_bfloat16 h = __float2bfloat16(w);
        g_B1h[n * 256 + k] = h;
        g_B1l[n * 256 + k] = __float2bfloat16(w - __bfloat162float(h));
    }
}

__global__ void convertA_kernel(const float* __restrict__ uf) {
    int i = blockIdx.x * blockDim.x + threadIdx.x;   // float4 index
    if (i < N_NODES * 64) {
        uint2 hh, ll;
        split4(((const float4*)uf)[i], hh, ll);
        *(uint2*)(g_Ah + (size_t)i * 4) = hh;
        *(uint2*)(g_Al + (size_t)i * 4) = ll;
    }
}

// ---------------- graph prep --------------------------------------------------
__global__ void init_kernel() {
    int i = blockIdx.x * blockDim.x + threadIdx.x;
    if (i < N_NODES) { g_deg[i] = 1.0f; g_count[i] = 0; }
}
__global__ void edge_prep_kernel(const int* __restrict__ ei, const float* __restrict__ ea) {
    int e = blockIdx.x * blockDim.x + threadIdx.x;
    if (e < N_EDGES) {
        int dst = ei[N_EDGES + e];
        atomicAdd(&g_deg[dst], ea[e]);
        atomicAdd(&g_count[dst], 1);
    }
}
__global__ void dinv_kernel() {
    int i = blockIdx.x * blockDim.x + threadIdx.x;
    if (i < N_NODES) g_dinv[i] = rsqrtf(g_deg[i]);
}

// parallel 3-phase scan
__global__ void scan_blocks_kernel() {
    __shared__ int wsum[8];
    int tid = threadIdx.x, lane = tid & 31, w = tid >> 5;
    int i = blockIdx.x * 256 + tid;
    int v = (i < N_NODES) ? g_count[i] : 0;
    int x = v;
    #pragma unroll
    for (int o = 1; o < 32; o <<= 1) {
        int y = __shfl_up_sync(0xffffffffu, x, o);
        if (lane >= o) x += y;
    }
    if (lane == 31) wsum[w] = x;
    __syncthreads();
    if (w == 0 && lane < 8) {
        int t = wsum[lane];
        #pragma unroll
        for (int o = 1; o < 8; o <<= 1) {
            int y = __shfl_up_sync(0xffu, t, o);
            if (lane >= o) t += y;
        }
        wsum[lane] = t;
    }
    __syncthreads();
    int wpre = (w == 0) ? 0 : wsum[w - 1];
    if (i < N_NODES) g_off[i] = wpre + x - v;
    if (tid == 255) g_bsum[blockIdx.x] = wsum[7];
}
__global__ void scan_tops_kernel() {
    __shared__ int wsum[8];
    int tid = threadIdx.x, lane = tid & 31, w = tid >> 5;
    int v = (tid < SCAN_BLOCKS) ? g_bsum[tid] : 0;
    int x = v;
    #pragma unroll
    for (int o = 1; o < 32; o <<= 1) {
        int y = __shfl_up_sync(0xffffffffu, x, o);
        if (lane >= o) x += y;
    }
    if (lane == 31) wsum[w] = x;
    __syncthreads();
    if (w == 0 && lane < 8) {
        int t = wsum[lane];
        #pragma unroll
        for (int o = 1; o < 8; o <<= 1) {
            int y = __shfl_up_sync(0xffu, t, o);
            if (lane >= o) t += y;
        }
        wsum[lane] = t;
    }
    __syncthreads();
    int wpre = (w == 0) ? 0 : wsum[w - 1];
    if (tid < SCAN_BLOCKS) g_btop[tid] = wpre + x - v;
}
__global__ void scan_apply_kernel() {
    int i = blockIdx.x * 256 + threadIdx.x;
    if (i < N_NODES) {
        int o = g_off[i] + g_btop[blockIdx.x];
        g_off[i] = o;
        g_fill[i] = o;
    }
    if (i == 0) g_off[N_NODES] = N_EDGES;
}
__global__ void fill_kernel(const int* __restrict__ ei) {
    int e = blockIdx.x * blockDim.x + threadIdx.x;
    if (e < N_EDGES) {
        int dst = ei[N_EDGES + e];
        int pos = atomicAdd(&g_fill[dst], 1);
        g_elist[pos] = e;
    }
}

// ---------------- GEMM1 (mma.sync bf16, pass-fused): h1 = x @ gcn1_W ----------
__global__ __launch_bounds__(256) void gemm1_mma_kernel(const float* __restrict__ x) {
    extern __shared__ char smem[];
    const int AH = 0, AL = 33792, BH = 67584, BL = 101376;
    uint32_t sb = smem_u32(smem);
    int tid = threadIdx.x, w = tid >> 5, lane = tid & 31;
    int row0 = blockIdx.x * 64;

    for (int i = tid; i < 64 * 64; i += 256) {
        int r = i >> 6, c4 = i & 63;
        float4 v = make_float4(0.f, 0.f, 0.f, 0.f);
        int row = row0 + r;
        if (row < N_NODES) v = *(const float4*)(x + (size_t)row * 256 + c4 * 4);
        uint2 hh, ll;
        split4(v, hh, ll);
        *(uint2*)(smem + AH + r * 528 + c4 * 8) = hh;
        *(uint2*)(smem + AL + r * 528 + c4 * 8) = ll;
    }
    for (int i = tid; i < 64 * 32; i += 256) {
        int n = i >> 5, j = i & 31;
        *(uint4*)(smem + BH + n * 528 + j * 16) = *(const uint4*)(g_B1h + n * 256 + j * 8);
        *(uint4*)(smem + BL + n * 528 + j * 16) = *(const uint4*)(g_B1l + n * 256 + j * 8);
    }
    __syncthreads();

    float c[4][4] = {};
    int ll16 = lane & 15;
    #pragma unroll 2
    for (int ks = 0; ks < 16; ks++) {
        int kg = ks * 16;
        uint32_t ah[4][4], al[4][4];
        #pragma unroll
        for (int mt = 0; mt < 4; mt++) {
            uint32_t off = (mt * 16 + ll16) * 528 + kg * 2 + ((lane >> 4) & 1) * 16;
            LDSM4(ah[mt][0], ah[mt][1], ah[mt][2], ah[mt][3], sb + AH + off);
            LDSM4(al[mt][0], al[mt][1], al[mt][2], al[mt][3], sb + AL + off);
        }
        uint32_t boff = (w * 8 + (ll16 & 7)) * 528 + kg * 2 + ((ll16 >> 3) & 1) * 16;
        uint32_t bh0, bh1, bl0, bl1;
        LDSM2(bh0, bh1, sb + BH + boff);
        LDSM2(bl0, bl1, sb + BL + boff);
        #pragma unroll
        for (int mt = 0; mt < 4; mt++) {
            MMA(c[mt], ah[mt], bh0, bh1);
            MMA(c[mt], al[mt], bh0, bh1);
            MMA(c[mt], ah[mt], bl0, bl1);
        }
    }
    int g = lane >> 2, tg = lane & 3;
    int col = w * 8 + tg * 2;
    #pragma unroll
    for (int mt = 0; mt < 4; mt++) {
        #pragma unroll
        for (int h = 0; h < 2; h++) {
            int row = row0 + mt * 16 + h * 8 + g;
            if (row < N_NODES)
                *(float2*)(g_h1 + (size_t)row * 64 + col) = make_float2(c[mt][h * 2], c[mt][h * 2 + 1]);
        }
    }
}

// ---------------- fused: CSR gather + self-loop + bias + relu + dot(v) --------
__global__ void gather1_kernel(const int* __restrict__ ei, const float* __restrict__ ea,
                               const float* __restrict__ b1) {
    int gtid = blockIdx.x * blockDim.x + threadIdx.x;
    int node = gtid >> 5;
    int lane = gtid & 31;
    if (node >= N_NODES) return;
    float dinvi = g_dinv[node];
    float d2 = dinvi * dinvi;
    const float* h1n = g_h1 + (size_t)node * 64;
    float acc0 = h1n[lane] * d2;
    float acc1 = h1n[lane + 32] * d2;
    int beg = g_off[node], end = g_off[node + 1];
    for (int j = beg; j < end; j++) {
        int e = g_elist[j];
        int src = ei[e];
        float norm = ea[e] * g_dinv[src] * dinvi;
        const float* h1s = g_h1 + (size_t)src * 64;
        acc0 += h1s[lane] * norm;
        acc1 += h1s[lane + 32] * norm;
    }
    float gg0 = fmaxf(acc0 + b1[lane], 0.f);
    float gg1 = fmaxf(acc1 + b1[lane + 32], 0.f);
    float p = gg0 * g_v[lane] + gg1 * g_v[lane + 32];
    #pragma unroll
    for (int o = 16; o > 0; o >>= 1) p += __shfl_xor_sync(0xffffffffu, p, o);
    if (lane == 0) { g_s[node] = p; g_sagg[node] = d2 * p; }
}

// ---------------- scalar layer-2 aggregation ----------------------------------
__global__ void gather2_kernel(const int* __restrict__ ei, const float* __restrict__ ea) {
    int i = blockIdx.x * blockDim.x + threadIdx.x;
    if (i >= N_NODES) return;
    float dinvi = g_dinv[i];
    float acc = g_sagg[i];
    int beg = g_off[i], end = g_off[i + 1];
    for (int j = beg; j < end; j++) {
        int e = g_elist[j];
        int src = ei[e];
        acc += ea[e] * g_dinv[src] * dinvi * g_s[src];
    }
    g_sagg[i] = acc;
}

// ---------------- fused MLP (mma.sync bf16, cp.async double-buffered) ---------
// CTA: M=32, N=256 (blockIdx.y half), K in 8 chunks of 32, double-buffered via
// cp.async. 256 thr / 8 warps, warp tile m32 x n32.
// SMEM: Ah 16896 | Al 16896 | Bbuf0 40960 | Bbuf1 40960 = 115712 -> 2 CTAs/SM.
// sred aliases the B region in the epilogue; bias/u read straight from global.
__global__ __launch_bounds__(256, 2) void mlp_mma_kernel(const float* __restrict__ b1) {
    extern __shared__ char smem[];
    const int AH = 0, AL = 16896, BB = 33792, BUF = 40960, BLO = 20480;
    uint32_t sb = smem_u32(smem);
    int tid = threadIdx.x, w = tid >> 5, lane = tid & 31;
    int row0 = blockIdx.x * 32;
    int ngrp = blockIdx.y;
    const __nv_bfloat16* Bhg = g_Bh + (size_t)ngrp * 256 * 256;
    const __nv_bfloat16* Blg = g_Bl + (size_t)ngrp * 256 * 256;

    // group 0: A (hi/lo, full K=256) + B chunk 0, all via cp.async
    #pragma unroll
    for (int p = 0; p < 4; p++) {
        int i = tid + 256 * p;
        int r = i >> 5, c = i & 31;
        int row = row0 + r;
        uint32_t sz = (row < N_NODES) ? 16u : 0u;
        size_t rr = (row < N_NODES) ? (size_t)row : 0;
        CPA16(sb + AH + r * 528 + c * 16, g_Ah + rr * 256 + c * 8, sz);
        CPA16(sb + AL + r * 528 + c * 16, g_Al + rr * 256 + c * 8, sz);
    }
    #pragma unroll
    for (int p = 0; p < 4; p++) {
        int i = tid + 256 * p;
        int n = i >> 2, j = i & 3;
        CPA16(sb + BB + n * 80 + j * 16, Bhg + n * 256 + j * 8, 16u);
        CPA16(sb + BB + BLO + n * 80 + j * 16, Blg + n * 256 + j * 8, 16u);
    }
    CP_COMMIT();

    float c[2][4][4] = {};
    int ll16 = lane & 15;
    int sub = (lane >> 3) & 3;

    #pragma unroll 1
    for (int ch = 0; ch < 8; ch++) {
        if (ch < 7) {
            uint32_t dst = sb + BB + ((ch + 1) & 1) * BUF;
            int kg = (ch + 1) * 32;
            #pragma unroll
            for (int p = 0; p < 4; p++) {
                int i = tid + 256 * p;
                int n = i >> 2, j = i & 3;
                CPA16(dst + n * 80 + j * 16, Bhg + n * 256 + kg + j * 8, 16u);
                CPA16(dst + BLO + n * 80 + j * 16, Blg + n * 256 + kg + j * 8, 16u);
            }
            CP_COMMIT();
            CP_WAIT(1);
        } else {
            CP_WAIT(0);
        }
        __syncthreads();

        uint32_t bbase = sb + BB + (ch & 1) * BUF;
        #pragma unroll
        for (int ks = 0; ks < 2; ks++) {
            int kk = ks * 16;
            int kg = ch * 32 + kk;
            uint32_t ah[2][4], al[2][4];
            #pragma unroll
            for (int mt = 0; mt < 2; mt++) {
                uint32_t off = (mt * 16 + ll16) * 528 + kg * 2 + ((lane >> 4) & 1) * 16;
                LDSM4(ah[mt][0], ah[mt][1], ah[mt][2], ah[mt][3], sb + AH + off);
                LDSM4(al[mt][0], al[mt][1], al[mt][2], al[mt][3], sb + AL + off);
            }
            uint32_t bh[4][2], bl[4][2];
            #pragma unroll
            for (int ntp = 0; ntp < 2; ntp++) {
                int noff = w * 32 + ntp * 16 + ((sub & 2) ? 8 : 0) + (lane & 7);
                uint32_t boff = noff * 80 + kk * 2 + (sub & 1) * 16;
                uint32_t r0, r1, r2, r3;
                LDSM4(r0, r1, r2, r3, bbase + boff);
                bh[ntp * 2][0] = r0; bh[ntp * 2][1] = r1;
                bh[ntp * 2 + 1][0] = r2; bh[ntp * 2 + 1][1] = r3;
                LDSM4(r0, r1, r2, r3, bbase + BLO + boff);
                bl[ntp * 2][0] = r0; bl[ntp * 2][1] = r1;
                bl[ntp * 2 + 1][0] = r2; bl[ntp * 2 + 1][1] = r3;
            }
            #pragma unroll
            for (int mt = 0; mt < 2; mt++)
                #pragma unroll
                for (int nt = 0; nt < 4; nt++) {
                    MMA(c[mt][nt], ah[mt], bh[nt][0], bh[nt][1]);
                    MMA(c[mt][nt], al[mt], bh[nt][0], bh[nt][1]);
                    MMA(c[mt][nt], ah[mt], bl[nt][0], bl[nt][1]);
                }
        }
        __syncthreads();
    }

    // epilogue: bias + relu + dot(u); quad-shuffle -> smem (aliases B) -> write
    float* sred = (float*)(smem + BB);
    const float* b1g = b1 + ngrp * 256;
    const float* ug  = g_u + ngrp * 256;
    int g = lane >> 2, tg = lane & 3;
    #pragma unroll
    for (int mt = 0; mt < 2; mt++) {
        float rs[2] = {0.f, 0.f};
        #pragma unroll
        for (int nt = 0; nt < 4; nt++) {
            int col = w * 32 + nt * 8 + tg * 2;
            float bb0 = b1g[col], uu0 = ug[col];
            float bb1 = b1g[col + 1], uu1 = ug[col + 1];
            #pragma unroll
            for (int h = 0; h < 2; h++) {
                float h0 = c[mt][nt][h * 2] + bb0;
                float h1 = c[mt][nt][h * 2 + 1] + bb1;
                if (h0 > 0.f) rs[h] += h0 * uu0;
                if (h1 > 0.f) rs[h] += h1 * uu1;
            }
        }
        #pragma unroll
        for (int h = 0; h < 2; h++) {
            rs[h] += __shfl_xor_sync(0xffffffffu, rs[h], 1);
            rs[h] += __shfl_xor_sync(0xffffffffu, rs[h], 2);
            if (tg == 0) sred[(mt * 16 + h * 8 + g) * 9 + w] = rs[h];
        }
    }
    __syncthreads();
    if (tid < 32) {
        float sum = 0.f;
        #pragma unroll
        for (int t = 0; t < 8; t++) sum += sred[tid * 9 + t];
        int row = row0 + tid;
        if (row < N_NODES) g_mlp[ngrp][row] = sum;
    }
}

// ---------------- final combine -----------------------------------------------
__global__ void final_kernel(float* __restrict__ out) {
    int i = blockIdx.x * blockDim.x + threadIdx.x;
    if (i < N_NODES)
        out[i] = g_mlp[0][i] + g_mlp[1][i] + g_sagg[i] + g_cconst;
}

// ------------------------------------------------------------------------------
extern "C" void kernel_launch(void* const* d_in, const int* in_sizes, int n_in,
                              void* d_out, int out_size) {
    const float* x   = (const float*)d_in[0];
    const int*   ei  = (const int*)d_in[1];
    const float* ea  = (const float*)d_in[2];
    const float* uf  = (const float*)d_in[3];
    const float* g1W = (const float*)d_in[4];
    const float* g1b = (const float*)d_in[5];
    const float* g2W = (const float*)d_in[6];
    const float* g2b = (const float*)d_in[7];
    const float* f1W = (const float*)d_in[8];
    const float* f1b = (const float*)d_in[9];
    const float* f2W = (const float*)d_in[10];
    const float* f2b = (const float*)d_in[11];
    const float* ffW = (const float*)d_in[12];
    const float* ffb = (const float*)d_in[13];
    float* out = (float*)d_out;

    static cudaStream_t s1 = nullptr, s2 = nullptr;
    static cudaEvent_t ev0, evG, ev1, ev2;
    if (!s1) {
        cudaStreamCreateWithFlags(&s1, cudaStreamNonBlocking);
        cudaStreamCreateWithFlags(&s2, cudaStreamNonBlocking);
        cudaEventCreateWithFlags(&ev0, cudaEventDisableTiming);
        cudaEventCreateWithFlags(&evG, cudaEventDisableTiming);
        cudaEventCreateWithFlags(&ev1, cudaEventDisableTiming);
        cudaEventCreateWithFlags(&ev2, cudaEventDisableTiming);
        cudaFuncSetAttribute(gemm1_mma_kernel, cudaFuncAttributeMaxDynamicSharedMemorySize, 135168);
        cudaFuncSetAttribute(mlp_mma_kernel, cudaFuncAttributeMaxDynamicSharedMemorySize, 115712);
    }

    // fork
    cudaEventRecord(ev0, 0);
    cudaStreamWaitEvent(s1, ev0, 0);
    cudaStreamWaitEvent(s2, ev0, 0);

    // s2: uf -> bf16 hi/lo split (only mlp depends on it)
    convertA_kernel<<<(N_NODES * 64 + 255) / 256, 256, 0, s2>>>(uf);
    cudaEventRecord(ev2, s2);

    // s1: graph prep
    init_kernel<<<(N_NODES + 255) / 256, 256, 0, s1>>>();
    edge_prep_kernel<<<(N_EDGES + 255) / 256, 256, 0, s1>>>(ei, ea);
    dinv_kernel<<<(N_NODES + 255) / 256, 256, 0, s1>>>();
    scan_blocks_kernel<<<SCAN_BLOCKS, 256, 0, s1>>>();
    scan_tops_kernel<<<1, 256, 0, s1>>>();
    scan_apply_kernel<<<SCAN_BLOCKS, 256, 0, s1>>>();
    fill_kernel<<<(N_EDGES + 255) / 256, 256, 0, s1>>>(ei);

    // main: weights + gemm1 (gathers depend on h1)
    precompute_kernel<<<1, 512>>>(g2W, g2b, f2W, f2b, ffW, ffb);
    convert_W_kernel<<<(256 * 512 + 256 * 64 + 255) / 256, 256>>>(f1W, g1W);
    gemm1_mma_kernel<<<(N_NODES + 63) / 64, 256, 135168>>>(x);
    cudaEventRecord(evG, 0);

    // s1 continues: gathers
    cudaStreamWaitEvent(s1, evG, 0);
    gather1_kernel<<<((size_t)N_NODES * 32 + 255) / 256, 256, 0, s1>>>(ei, ea, g1b);
    gather2_kernel<<<(N_NODES + 255) / 256, 256, 0, s1>>>(ei, ea);
    cudaEventRecord(ev1, s1);

    // main: MLP GEMM (needs convertA) overlaps the graph branch
    cudaStreamWaitEvent(0, ev2, 0);
    mlp_mma_kernel<<<dim3((N_NODES + 31) / 32, 2), 256, 115712>>>(f1b);

    // join + combine
    cudaStreamWaitEvent(0, ev1, 0);
    final_kernel<<<(N_NODES + 255) / 256, 256>>>(out);
}

// round 17
// speedup vs baseline: 1.1162x; 1.0375x over previous
#include <cuda_runtime.h>
#include <cuda_bf16.h>
#include <cstdint>

#define N_NODES 50000
#define N_EDGES 800000
#define SCAN_BLOCKS 196

// ---------------- scratch (device globals; no runtime allocation) -------------
__device__ float g_deg[N_NODES];
__device__ float g_dinv[N_NODES];
__device__ int   g_count[N_NODES];
__device__ int   g_off[N_NODES + 1];
__device__ int   g_fill[N_NODES];
__device__ int   g_bsum[SCAN_BLOCKS];
__device__ int   g_btop[SCAN_BLOCKS];
__device__ int   g_elist[N_EDGES];
__device__ float g_h1[(size_t)N_NODES * 64];
__device__ float g_s[N_NODES];
__device__ float g_sagg[N_NODES];
__device__ float g_v[64];     // gcn2_W @ w_gnn
__device__ float g_u[512];    // fc2_W  @ w_mlp
__device__ float g_cconst;    // fcf_b + fc2_b.w_mlp + gcn2_b.w_gnn
__device__ float g_mlp[2][N_NODES];                    // per-N-half MLP partials
// bf16 hi/lo operands
__device__ __nv_bfloat16 g_Ah[(size_t)N_NODES * 256];  // uf hi
__device__ __nv_bfloat16 g_Al[(size_t)N_NODES * 256];  // uf lo
__device__ __nv_bfloat16 g_Bh[512 * 256];              // fc1_W^T hi  [n][k]
__device__ __nv_bfloat16 g_Bl[512 * 256];              // fc1_W^T lo
__device__ __nv_bfloat16 g_B1h[64 * 256];              // gcn1_W^T hi
__device__ __nv_bfloat16 g_B1l[64 * 256];              // gcn1_W^T lo

// ---------------- PTX helpers (baseline sm_80+ features only) ------------------
__device__ __forceinline__ uint32_t smem_u32(const void* p) {
    uint32_t a;
    asm("{ .reg .u64 t; cvta.to.shared.u64 t, %1; cvt.u32.u64 %0, t; }" : "=r"(a) : "l"(p));
    return a;
}
#define LDSM4(r0, r1, r2, r3, a) \
    asm volatile("ldmatrix.sync.aligned.m8n8.x4.shared.b16 {%0,%1,%2,%3}, [%4];" \
                 : "=r"(r0), "=r"(r1), "=r"(r2), "=r"(r3) : "r"(a))
#define LDSM2(r0, r1, a) \
    asm volatile("ldmatrix.sync.aligned.m8n8.x2.shared.b16 {%0,%1}, [%2];" \
                 : "=r"(r0), "=r"(r1) : "r"(a))
#define MMA(c, a, b0, b1) \
    asm volatile("mma.sync.aligned.m16n8k16.row.col.f32.bf16.bf16.f32 " \
                 "{%0,%1,%2,%3},{%4,%5,%6,%7},{%8,%9},{%0,%1,%2,%3};" \
                 : "+f"((c)[0]), "+f"((c)[1]), "+f"((c)[2]), "+f"((c)[3]) \
                 : "r"((a)[0]), "r"((a)[1]), "r"((a)[2]), "r"((a)[3]), "r"(b0), "r"(b1))
#define CPA16(d, s, sz) \
    asm volatile("cp.async.cg.shared.global [%0], [%1], 16, %2;" :: "r"(d), "l"(s), "r"(sz))
#define CP_COMMIT() asm volatile("cp.async.commit_group;" ::: "memory")
#define CP_WAIT(n)  asm volatile("cp.async.wait_group %0;" :: "n"(n) : "memory")

__device__ __forceinline__ uint32_t pack_bf(__nv_bfloat16 a, __nv_bfloat16 b) {
    __nv_bfloat162 t(a, b);
    return *(uint32_t*)&t;
}
__device__ __forceinline__ void split4(float4 v, uint2& hh, uint2& ll) {
    float vv[4] = {v.x, v.y, v.z, v.w};
    __nv_bfloat16 h[4], l[4];
    #pragma unroll
    for (int j = 0; j < 4; j++) {
        h[j] = __float2bfloat16(vv[j]);
        l[j] = __float2bfloat16(vv[j] - __bfloat162float(h[j]));
    }
    hh = make_uint2(pack_bf(h[0], h[1]), pack_bf(h[2], h[3]));
    ll = make_uint2(pack_bf(l[0], l[1]), pack_bf(l[2], l[3]));
}

// ---------------- tiny precompute: collapse trailing GEMMs --------------------
__global__ void precompute_kernel(const float* __restrict__ g2W, const float* __restrict__ g2b,
                                  const float* __restrict__ f2W, const float* __restrict__ f2b,
                                  const float* __restrict__ ffW, const float* __restrict__ ffb) {
    int tid = threadIdx.x;
    if (tid < 512) {
        float acc = 0.f;
        #pragma unroll 8
        for (int c = 0; c < 64; c++) acc += f2W[tid * 64 + c] * ffW[c];
        g_u[tid] = acc;
    }
    if (tid < 64) {
        float acc = 0.f;
        #pragma unroll 8
        for (int c = 0; c < 64; c++) acc += g2W[tid * 64 + c] * ffW[64 + c];
        g_v[tid] = acc;
    }
    if (tid == 0) {
        float acc = ffb[0];
        for (int c = 0; c < 64; c++) acc += f2b[c] * ffW[c] + g2b[c] * ffW[64 + c];
        g_cconst = acc;
    }
}

__global__ void convert_W_kernel(const float* __restrict__ f1W, const float* __restrict__ g1W) {
    int idx = blockIdx.x * blockDim.x + threadIdx.x;
    if (idx < 256 * 512) {
        int k = idx / 512, n = idx % 512;
        float w = f1W[idx];
        __nv_bfloat16 h = __float2bfloat16(w);
        g_Bh[n * 256 + k] = h;
        g_Bl[n * 256 + k] = __float2bfloat16(w - __bfloat162float(h));
    } else if (idx < 256 * 512 + 256 * 64) {
        int i2 = idx - 256 * 512;
        int k = i2 / 64, n = i2 % 64;
        float w = g1W[i2];
        __nv_bfloat16 h = __float2bfloat16(w);
        g_B1h[n * 256 + k] = h;
        g_B1l[n * 256 + k] = __float2bfloat16(w - __bfloat162float(h));
    }
}

__global__ void convertA_kernel(const float* __restrict__ uf) {
    int i = blockIdx.x * blockDim.x + threadIdx.x;   // float4 index
    if (i < N_NODES * 64) {
        uint2 hh, ll;
        split4(((const float4*)uf)[i], hh, ll);
        *(uint2*)(g_Ah + (size_t)i * 4) = hh;
        *(uint2*)(g_Al + (size_t)i * 4) = ll;
    }
}

// ---------------- graph prep --------------------------------------------------
__global__ void init_kernel() {
    int i = blockIdx.x * blockDim.x + threadIdx.x;
    if (i < N_NODES) { g_deg[i] = 1.0f; g_count[i] = 0; }
}
__global__ void edge_prep_kernel(const int* __restrict__ ei, const float* __restrict__ ea) {
    int e = blockIdx.x * blockDim.x + threadIdx.x;
    if (e < N_EDGES) {
        int dst = ei[N_EDGES + e];
        atomicAdd(&g_deg[dst], ea[e]);
        atomicAdd(&g_count[dst], 1);
    }
}
__global__ void dinv_kernel() {
    int i = blockIdx.x * blockDim.x + threadIdx.x;
    if (i < N_NODES) g_dinv[i] = rsqrtf(g_deg[i]);
}

// parallel 3-phase scan
__global__ void scan_blocks_kernel() {
    __shared__ int wsum[8];
    int tid = threadIdx.x, lane = tid & 31, w = tid >> 5;
    int i = blockIdx.x * 256 + tid;
    int v = (i < N_NODES) ? g_count[i] : 0;
    int x = v;
    #pragma unroll
    for (int o = 1; o < 32; o <<= 1) {
        int y = __shfl_up_sync(0xffffffffu, x, o);
        if (lane >= o) x += y;
    }
    if (lane == 31) wsum[w] = x;
    __syncthreads();
    if (w == 0 && lane < 8) {
        int t = wsum[lane];
        #pragma unroll
        for (int o = 1; o < 8; o <<= 1) {
            int y = __shfl_up_sync(0xffu, t, o);
            if (lane >= o) t += y;
        }
        wsum[lane] = t;
    }
    __syncthreads();
    int wpre = (w == 0) ? 0 : wsum[w - 1];
    if (i < N_NODES) g_off[i] = wpre + x - v;
    if (tid == 255) g_bsum[blockIdx.x] = wsum[7];
}
__global__ void scan_tops_kernel() {
    __shared__ int wsum[8];
    int tid = threadIdx.x, lane = tid & 31, w = tid >> 5;
    int v = (tid < SCAN_BLOCKS) ? g_bsum[tid] : 0;
    int x = v;
    #pragma unroll
    for (int o = 1; o < 32; o <<= 1) {
        int y = __shfl_up_sync(0xffffffffu, x, o);
        if (lane >= o) x += y;
    }
    if (lane == 31) wsum[w] = x;
    __syncthreads();
    if (w == 0 && lane < 8) {
        int t = wsum[lane];
        #pragma unroll
        for (int o = 1; o < 8; o <<= 1) {
            int y = __shfl_up_sync(0xffu, t, o);
            if (lane >= o) t += y;
        }
        wsum[lane] = t;
    }
    __syncthreads();
    int wpre = (w == 0) ? 0 : wsum[w - 1];
    if (tid < SCAN_BLOCKS) g_btop[tid] = wpre + x - v;
}
__global__ void scan_apply_kernel() {
    int i = blockIdx.x * 256 + threadIdx.x;
    if (i < N_NODES) {
        int o = g_off[i] + g_btop[blockIdx.x];
        g_off[i] = o;
        g_fill[i] = o;
    }
    if (i == 0) g_off[N_NODES] = N_EDGES;
}
__global__ void fill_kernel(const int* __restrict__ ei) {
    int e = blockIdx.x * blockDim.x + threadIdx.x;
    if (e < N_EDGES) {
        int dst = ei[N_EDGES + e];
        int pos = atomicAdd(&g_fill[dst], 1);
        g_elist[pos] = e;
    }
}

// ---------------- GEMM1 (mma.sync bf16, pass-fused): h1 = x @ gcn1_W ----------
__global__ __launch_bounds__(256) void gemm1_mma_kernel(const float* __restrict__ x) {
    extern __shared__ char smem[];
    const int AH = 0, AL = 33792, BH = 67584, BL = 101376;
    uint32_t sb = smem_u32(smem);
    int tid = threadIdx.x, w = tid >> 5, lane = tid & 31;
    int row0 = blockIdx.x * 64;

    for (int i = tid; i < 64 * 64; i += 256) {
        int r = i >> 6, c4 = i & 63;
        float4 v = make_float4(0.f, 0.f, 0.f, 0.f);
        int row = row0 + r;
        if (row < N_NODES) v = *(const float4*)(x + (size_t)row * 256 + c4 * 4);
        uint2 hh, ll;
        split4(v, hh, ll);
        *(uint2*)(smem + AH + r * 528 + c4 * 8) = hh;
        *(uint2*)(smem + AL + r * 528 + c4 * 8) = ll;
    }
    for (int i = tid; i < 64 * 32; i += 256) {
        int n = i >> 5, j = i & 31;
        *(uint4*)(smem + BH + n * 528 + j * 16) = *(const uint4*)(g_B1h + n * 256 + j * 8);
        *(uint4*)(smem + BL + n * 528 + j * 16) = *(const uint4*)(g_B1l + n * 256 + j * 8);
    }
    __syncthreads();

    float c[4][4] = {};
    int ll16 = lane & 15;
    #pragma unroll 2
    for (int ks = 0; ks < 16; ks++) {
        int kg = ks * 16;
        uint32_t ah[4][4], al[4][4];
        #pragma unroll
        for (int mt = 0; mt < 4; mt++) {
            uint32_t off = (mt * 16 + ll16) * 528 + kg * 2 + ((lane >> 4) & 1) * 16;
            LDSM4(ah[mt][0], ah[mt][1], ah[mt][2], ah[mt][3], sb + AH + off);
            LDSM4(al[mt][0], al[mt][1], al[mt][2], al[mt][3], sb + AL + off);
        }
        uint32_t boff = (w * 8 + (ll16 & 7)) * 528 + kg * 2 + ((ll16 >> 3) & 1) * 16;
        uint32_t bh0, bh1, bl0, bl1;
        LDSM2(bh0, bh1, sb + BH + boff);
        LDSM2(bl0, bl1, sb + BL + boff);
        #pragma unroll
        for (int mt = 0; mt < 4; mt++) {
            MMA(c[mt], ah[mt], bh0, bh1);
            MMA(c[mt], al[mt], bh0, bh1);
            MMA(c[mt], ah[mt], bl0, bl1);
        }
    }
    int g = lane >> 2, tg = lane & 3;
    int col = w * 8 + tg * 2;
    #pragma unroll
    for (int mt = 0; mt < 4; mt++) {
        #pragma unroll
        for (int h = 0; h < 2; h++) {
            int row = row0 + mt * 16 + h * 8 + g;
            if (row < N_NODES)
                *(float2*)(g_h1 + (size_t)row * 64 + col) = make_float2(c[mt][h * 2], c[mt][h * 2 + 1]);
        }
    }
}

// ---------------- fused: CSR gather + self-loop + bias + relu + dot(v) --------
__global__ void gather1_kernel(const int* __restrict__ ei, const float* __restrict__ ea,
                               const float* __restrict__ b1) {
    int gtid = blockIdx.x * blockDim.x + threadIdx.x;
    int node = gtid >> 5;
    int lane = gtid & 31;
    if (node >= N_NODES) return;
    float dinvi = g_dinv[node];
    float d2 = dinvi * dinvi;
    const float* h1n = g_h1 + (size_t)node * 64;
    float acc0 = h1n[lane] * d2;
    float acc1 = h1n[lane + 32] * d2;
    int beg = g_off[node], end = g_off[node + 1];
    for (int j = beg; j < end; j++) {
        int e = g_elist[j];
        int src = ei[e];
        float norm = ea[e] * g_dinv[src] * dinvi;
        const float* h1s = g_h1 + (size_t)src * 64;
        acc0 += h1s[lane] * norm;
        acc1 += h1s[lane + 32] * norm;
    }
    float gg0 = fmaxf(acc0 + b1[lane], 0.f);
    float gg1 = fmaxf(acc1 + b1[lane + 32], 0.f);
    float p = gg0 * g_v[lane] + gg1 * g_v[lane + 32];
    #pragma unroll
    for (int o = 16; o > 0; o >>= 1) p += __shfl_xor_sync(0xffffffffu, p, o);
    if (lane == 0) { g_s[node] = p; g_sagg[node] = d2 * p; }
}

// ---------------- scalar layer-2 aggregation ----------------------------------
__global__ void gather2_kernel(const int* __restrict__ ei, const float* __restrict__ ea) {
    int i = blockIdx.x * blockDim.x + threadIdx.x;
    if (i >= N_NODES) return;
    float dinvi = g_dinv[i];
    float acc = g_sagg[i];
    int beg = g_off[i], end = g_off[i + 1];
    for (int j = beg; j < end; j++) {
        int e = g_elist[j];
        int src = ei[e];
        acc += ea[e] * g_dinv[src] * dinvi * g_s[src];
    }
    g_sagg[i] = acc;
}

// ---------------- fused MLP (mma.sync bf16, M=64, 3-stage cp.async) -----------
// CTA: M=64, N=256 (blockIdx.y half), K in 8 chunks of 32, TRIPLE-buffered via
// cp.async (prefetch depth 2). 256 thr / 8 warps, warp tile m64 x n32 (mt=4).
// SMEM: Ah 33792 | Al 33792 | B 3 x 40960 = 190464 B -> 1 CTA/SM.
// sred aliases the B region in the epilogue; bias/u read straight from global.
__global__ __launch_bounds__(256) void mlp_mma_kernel(const float* __restrict__ b1) {
    extern __shared__ char smem[];
    const int AH = 0, AL = 33792, BB = 67584, BUF = 40960, BLO = 20480;
    uint32_t sb = smem_u32(smem);
    int tid = threadIdx.x, w = tid >> 5, lane = tid & 31;
    int row0 = blockIdx.x * 64;
    int ngrp = blockIdx.y;
    const __nv_bfloat16* Bhg = g_Bh + (size_t)ngrp * 256 * 256;
    const __nv_bfloat16* Blg = g_Bl + (size_t)ngrp * 256 * 256;

    // group 0: A (hi/lo, full K=256) + B chunk 0; group 1: B chunk 1
    #pragma unroll
    for (int p = 0; p < 8; p++) {
        int i = tid + 256 * p;
        int r = i >> 5, c = i & 31;
        int row = row0 + r;
        uint32_t sz = (row < N_NODES) ? 16u : 0u;
        size_t rr = (row < N_NODES) ? (size_t)row : 0;
        CPA16(sb + AH + r * 528 + c * 16, g_Ah + rr * 256 + c * 8, sz);
        CPA16(sb + AL + r * 528 + c * 16, g_Al + rr * 256 + c * 8, sz);
    }
    #pragma unroll
    for (int p = 0; p < 8; p++) {
        int i = tid + 256 * p;
        int n = i >> 2, j = i & 3;
        if (p < 4) {
            CPA16(sb + BB + n * 80 + j * 16, Bhg + n * 256 + j * 8, 16u);
            CPA16(sb + BB + BLO + n * 80 + j * 16, Blg + n * 256 + j * 8, 16u);
        }
    }
    CP_COMMIT();
    #pragma unroll
    for (int p = 0; p < 4; p++) {
        int i = tid + 256 * p;
        int n = i >> 2, j = i & 3;
        CPA16(sb + BB + BUF + n * 80 + j * 16, Bhg + n * 256 + 32 + j * 8, 16u);
        CPA16(sb + BB + BUF + BLO + n * 80 + j * 16, Blg + n * 256 + 32 + j * 8, 16u);
    }
    CP_COMMIT();

    float c[4][4][4] = {};
    int ll16 = lane & 15;
    int sub = (lane >> 3) & 3;

    #pragma unroll 1
    for (int ch = 0; ch < 8; ch++) {
        if (ch + 2 < 8) {
            int cn = ch + 2;
            int bi = cn % 3;
            uint32_t dst = sb + BB + bi * BUF;
            int kg = cn * 32;
            #pragma unroll
            for (int p = 0; p < 4; p++) {
                int i = tid + 256 * p;
                int n = i >> 2, j = i & 3;
                CPA16(dst + n * 80 + j * 16, Bhg + n * 256 + kg + j * 8, 16u);
                CPA16(dst + BLO + n * 80 + j * 16, Blg + n * 256 + kg + j * 8, 16u);
            }
            CP_COMMIT();
        }
        if (ch < 6) CP_WAIT(2);
        else if (ch == 6) CP_WAIT(1);
        else CP_WAIT(0);
        __syncthreads();

        uint32_t bbase = sb + BB + (ch % 3) * BUF;
        #pragma unroll
        for (int ks = 0; ks < 2; ks++) {
            int kk = ks * 16;
            int kg = ch * 32 + kk;
            uint32_t ah[4][4], al[4][4];
            #pragma unroll
            for (int mt = 0; mt < 4; mt++) {
                uint32_t off = (mt * 16 + ll16) * 528 + kg * 2 + ((lane >> 4) & 1) * 16;
                LDSM4(ah[mt][0], ah[mt][1], ah[mt][2], ah[mt][3], sb + AH + off);
                LDSM4(al[mt][0], al[mt][1], al[mt][2], al[mt][3], sb + AL + off);
            }
            uint32_t bh[4][2], bl[4][2];
            #pragma unroll
            for (int ntp = 0; ntp < 2; ntp++) {
                int noff = w * 32 + ntp * 16 + ((sub & 2) ? 8 : 0) + (lane & 7);
                uint32_t boff = noff * 80 + kk * 2 + (sub & 1) * 16;
                uint32_t r0, r1, r2, r3;
                LDSM4(r0, r1, r2, r3, bbase + boff);
                bh[ntp * 2][0] = r0; bh[ntp * 2][1] = r1;
                bh[ntp * 2 + 1][0] = r2; bh[ntp * 2 + 1][1] = r3;
                LDSM4(r0, r1, r2, r3, bbase + BLO + boff);
                bl[ntp * 2][0] = r0; bl[ntp * 2][1] = r1;
                bl[ntp * 2 + 1][0] = r2; bl[ntp * 2 + 1][1] = r3;
            }
            #pragma unroll
            for (int mt = 0; mt < 4; mt++)
                #pragma unroll
                for (int nt = 0; nt < 4; nt++) {
                    MMA(c[mt][nt], ah[mt], bh[nt][0], bh[nt][1]);
                    MMA(c[mt][nt], al[mt], bh[nt][0], bh[nt][1]);
                    MMA(c[mt][nt], ah[mt], bl[nt][0], bl[nt][1]);
                }
        }
        __syncthreads();
    }

    // epilogue: bias + relu + dot(u); quad-shuffle -> smem (aliases B) -> write
    float* sred = (float*)(smem + BB);
    const float* b1g = b1 + ngrp * 256;
    const float* ug  = g_u + ngrp * 256;
    int g = lane >> 2, tg = lane & 3;
    #pragma unroll
    for (int mt = 0; mt < 4; mt++) {
        float rs[2] = {0.f, 0.f};
        #pragma unroll
        for (int nt = 0; nt < 4; nt++) {
            int col = w * 32 + nt * 8 + tg * 2;
            float bb0 = b1g[col], uu0 = ug[col];
            float bb1 = b1g[col + 1], uu1 = ug[col + 1];
            #pragma unroll
            for (int h = 0; h < 2; h++) {
                float h0 = c[mt][nt][h * 2] + bb0;
                float h1 = c[mt][nt][h * 2 + 1] + bb1;
                if (h0 > 0.f) rs[h] += h0 * uu0;
                if (h1 > 0.f) rs[h] += h1 * uu1;
            }
        }
        #pragma unroll
        for (int h = 0; h < 2; h++) {
            rs[h] += __shfl_xor_sync(0xffffffffu, rs[h], 1);
            rs[h] += __shfl_xor_sync(0xffffffffu, rs[h], 2);
            if (tg == 0) sred[(mt * 16 + h * 8 + g) * 9 + w] = rs[h];
        }
    }
    __syncthreads();
    if (tid < 64) {
        float sum = 0.f;
        #pragma unroll
        for (int t = 0; t < 8; t++) sum += sred[tid * 9 + t];
        int row = row0 + tid;
        if (row < N_NODES) g_mlp[ngrp][row] = sum;
    }
}

// ---------------- final combine -----------------------------------------------
__global__ void final_kernel(float* __restrict__ out) {
    int i = blockIdx.x * blockDim.x + threadIdx.x;
    if (i < N_NODES)
        out[i] = g_mlp[0][i] + g_mlp[1][i] + g_sagg[i] + g_cconst;
}

// ------------------------------------------------------------------------------
extern "C" void kernel_launch(void* const* d_in, const int* in_sizes, int n_in,
                              void* d_out, int out_size) {
    const float* x   = (const float*)d_in[0];
    const int*   ei  = (const int*)d_in[1];
    const float* ea  = (const float*)d_in[2];
    const float* uf  = (const float*)d_in[3];
    const float* g1W = (const float*)d_in[4];
    const float* g1b = (const float*)d_in[5];
    const float* g2W = (const float*)d_in[6];
    const float* g2b = (const float*)d_in[7];
    const float* f1W = (const float*)d_in[8];
    const float* f1b = (const float*)d_in[9];
    const float* f2W = (const float*)d_in[10];
    const float* f2b = (const float*)d_in[11];
    const float* ffW = (const float*)d_in[12];
    const float* ffb = (const float*)d_in[13];
    float* out = (float*)d_out;

    static cudaStream_t s1 = nullptr, s2 = nullptr;
    static cudaEvent_t ev0, evG, ev1, ev2;
    if (!s1) {
        cudaStreamCreateWithFlags(&s1, cudaStreamNonBlocking);
        cudaStreamCreateWithFlags(&s2, cudaStreamNonBlocking);
        cudaEventCreateWithFlags(&ev0, cudaEventDisableTiming);
        cudaEventCreateWithFlags(&evG, cudaEventDisableTiming);
        cudaEventCreateWithFlags(&ev1, cudaEventDisableTiming);
        cudaEventCreateWithFlags(&ev2, cudaEventDisableTiming);
        cudaFuncSetAttribute(gemm1_mma_kernel, cudaFuncAttributeMaxDynamicSharedMemorySize, 135168);
        cudaFuncSetAttribute(mlp_mma_kernel, cudaFuncAttributeMaxDynamicSharedMemorySize, 190464);
    }

    // fork
    cudaEventRecord(ev0, 0);
    cudaStreamWaitEvent(s1, ev0, 0);
    cudaStreamWaitEvent(s2, ev0, 0);

    // s2: uf -> bf16 hi/lo split (only mlp depends on it)
    convertA_kernel<<<(N_NODES * 64 + 255) / 256, 256, 0, s2>>>(uf);
    cudaEventRecord(ev2, s2);

    // s1: graph prep
    init_kernel<<<(N_NODES + 255) / 256, 256, 0, s1>>>();
    edge_prep_kernel<<<(N_EDGES + 255) / 256, 256, 0, s1>>>(ei, ea);
    dinv_kernel<<<(N_NODES + 255) / 256, 256, 0, s1>>>();
    scan_blocks_kernel<<<SCAN_BLOCKS, 256, 0, s1>>>();
    scan_tops_kernel<<<1, 256, 0, s1>>>();
    scan_apply_kernel<<<SCAN_BLOCKS, 256, 0, s1>>>();
    fill_kernel<<<(N_EDGES + 255) / 256, 256, 0, s1>>>(ei);

    // main: weights + gemm1 (gathers depend on h1)
    precompute_kernel<<<1, 512>>>(g2W, g2b, f2W, f2b, ffW, ffb);
    convert_W_kernel<<<(256 * 512 + 256 * 64 + 255) / 256, 256>>>(f1W, g1W);
    gemm1_mma_kernel<<<(N_NODES + 63) / 64, 256, 135168>>>(x);
    cudaEventRecord(evG, 0);

    // s1 continues: gathers
    cudaStreamWaitEvent(s1, evG, 0);
    gather1_kernel<<<((size_t)N_NODES * 32 + 255) / 256, 256, 0, s1>>>(ei, ea, g1b);
    gather2_kernel<<<(N_NODES + 255) / 256, 256, 0, s1>>>(ei, ea);
    cudaEventRecord(ev1, s1);

    // main: MLP GEMM (needs convertA) overlaps the graph branch
    cudaStreamWaitEvent(0, ev2, 0);
    mlp_mma_kernel<<<dim3((N_NODES + 63) / 64, 2), 256, 190464>>>(f1b);

    // join + combine
    cudaStreamWaitEvent(0, ev1, 0);
    final_kernel<<<(N_NODES + 255) / 256, 256>>>(out);
}